// round 16
// baseline (speedup 1.0000x reference)
#include <cuda_runtime.h>
#include <cuda_fp16.h>
#include <math.h>
#include <stdint.h>

#define N_TOK   16384
#define DDIM    2048
#define NEXP    64
#define TM      32
#define NKS     (DDIM / 16)     // 128 k-steps of 16
#define NIT     (DDIM / 32)     // 64 iterations of 2 k-steps
#define TOPK    8
#define THREADS 256
#define LPAD    66

#define WSC       1024.0f           // 2^10 on W only
#define SCALE_INV 9.765625e-04f     // 2^-10

// B fragments (pi-permuted k), hi/lo interleaved: [ks][nb*32+lane]={hi0,hi1,lo0,lo1}
__device__ __align__(128) uint4 g_Bfrag[NKS * 256];

static __device__ __forceinline__ uint32_t h2u(__half2 h) {
    return reinterpret_cast<uint32_t&>(h);
}

static __device__ __forceinline__ void hmma(float* c, const uint32_t* a,
                                            uint32_t b0, uint32_t b1) {
    asm("mma.sync.aligned.m16n8k16.row.col.f32.f16.f16.f32 "
        "{%0,%1,%2,%3}, {%4,%5,%6,%7}, {%8,%9}, {%0,%1,%2,%3};"
        : "+f"(c[0]), "+f"(c[1]), "+f"(c[2]), "+f"(c[3])
        : "r"(a[0]), "r"(a[1]), "r"(a[2]), "r"(a[3]), "r"(b0), "r"(b1));
}

// split 2 floats -> hi half2 + lo residual half2
static __device__ __forceinline__ void split2(float v0, float v1,
                                              uint32_t& hi, uint32_t& lo) {
    __half2 h = __floats2half2_rn(v0, v1);
    float2 hf = __half22float2(h);
    __half2 r = __floats2half2_rn(v0 - hf.x, v1 - hf.y);
    hi = h2u(h); lo = h2u(r);
}

// r0 = row g float4, r1 = row g+8 float4 (one pi-permuted k-step)
static __device__ __forceinline__ void cvtf4(float4 r0, float4 r1,
                                             uint32_t* ahi, uint32_t* alo) {
    split2(r0.x, r0.y, ahi[0], alo[0]);
    split2(r1.x, r1.y, ahi[1], alo[1]);
    split2(r0.z, r0.w, ahi[2], alo[2]);
    split2(r1.z, r1.w, ahi[3], alo[3]);
}

// ---- prep: W -> pi-permuted fragments (lane t=l&3 slots hold cols 4t..4t+3) ----
__global__ void __launch_bounds__(256) wprep_kernel(const float* __restrict__ W) {
    int idx = blockIdx.x * 256 + threadIdx.x;        // 32768 = (ks, nb, lane)
    int l = idx & 31, nb = (idx >> 5) & 7, ks = idx >> 8;
    int n = nb * 8 + (l >> 2);
    int k = ks * 16 + (l & 3) * 4;
    float4 w = *(const float4*)(W + (size_t)n * DDIM + k);
    float a0 = w.x * WSC, a1 = w.y * WSC, a2 = w.z * WSC, a3 = w.w * WSC;
    uint32_t h0, l0, h1, l1;
    split2(a0, a1, h0, l0);
    split2(a2, a3, h1, l1);
    g_Bfrag[ks * 256 + nb * 32 + l] = make_uint4(h0, h1, l0, l1);
}

static __device__ __forceinline__ void ldB2(uint4 b[2], const uint4* gb, int ks) {
    const uint4* p = gb + ks * 256;
    b[0] = __ldg(p);
    b[1] = __ldg(p + 32);
}

static __device__ __forceinline__ void mma_step2(float acc[2][4],
                                                 const uint32_t* ahi, const uint32_t* alo,
                                                 const uint4 b[2]) {
    #pragma unroll
    for (int nb = 0; nb < 2; nb++) {
        hmma(acc[nb], ahi, b[nb].x, b[nb].y);
        hmma(acc[nb], ahi, b[nb].z, b[nb].w);
        hmma(acc[nb], alo, b[nb].x, b[nb].y);
    }
}

// ---- fused router: TM=32, warp = (2 rg x 4 ns), 3 CTAs/SM, zero mainloop sync ----
__global__ void __launch_bounds__(THREADS, 3)
router_kernel(const float* __restrict__ x, const float* __restrict__ bias,
              float* __restrict__ out) {
    __shared__ float logits[TM][LPAD];

    const int tid = threadIdx.x;
    const int wid = tid >> 5, l = tid & 31;
    const int rg  = wid & 1;           // row group: rows rg*16 .. rg*16+15
    const int ns  = wid >> 1;          // expert quarter: nb_global = ns*2 + nb
    const int g = l >> 2, kq = (l & 3) * 4;
    const int t0 = blockIdx.x * TM;

    const float* xr0 = x + (size_t)(t0 + rg * 16 + g) * DDIM + kq;
    const float* xr1 = xr0 + 8 * DDIM;
    const uint4* gb = g_Bfrag + ns * 64 + l;      // +nb*32 applied in ldB2

    float acc[2][4];
    #pragma unroll
    for (int nb = 0; nb < 2; nb++)
        #pragma unroll
        for (int c = 0; c < 4; c++) acc[nb][c] = 0.0f;

    // A raw for iter 0: 2 k-steps x 2 rows
    float4 raw[4];
    #pragma unroll
    for (int s = 0; s < 2; s++) {
        raw[s * 2 + 0] = *(const float4*)(xr0 + s * 16);
        raw[s * 2 + 1] = *(const float4*)(xr1 + s * 16);
    }

    uint4 bc[2], bn[2];
    ldB2(bc, gb, 0);

    for (int it = 0; it < NIT; it++) {
        const int ksA = it * 2;
        const int kn = ((it + 1 < NIT) ? (it + 1) : it) * 32;

        uint32_t ahi0[4], alo0[4], ahi1[4], alo1[4];
        cvtf4(raw[0], raw[1], ahi0, alo0);
        cvtf4(raw[2], raw[3], ahi1, alo1);

        // prefetch A raw for next iter (4 x LDG.128)
        #pragma unroll
        for (int s = 0; s < 2; s++) {
            raw[s * 2 + 0] = *(const float4*)(xr0 + kn + s * 16);
            raw[s * 2 + 1] = *(const float4*)(xr1 + kn + s * 16);
        }

        ldB2(bn, gb, ksA + 1);
        mma_step2(acc, ahi0, alo0, bc);
        ldB2(bc, gb, (it + 1 < NIT) ? ksA + 2 : ksA + 1);
        mma_step2(acc, ahi1, alo1, bn);
    }

    // ---- each warp owns its 16x16 logits block: direct write, no combine ----
    const int r0 = rg * 16 + g;
    const int kp = (l & 3) * 2;          // D-frag columns (unpermuted)
    #pragma unroll
    for (int nb = 0; nb < 2; nb++) {
        int c0 = (ns * 2 + nb) * 8 + kp;
        *(float2*)&logits[r0][c0]     = make_float2(acc[nb][0], acc[nb][1]);
        *(float2*)&logits[r0 + 8][c0] = make_float2(acc[nb][2], acc[nb][3]);
    }
    __syncthreads();

    if (tid < TM) {
        const float* p = &logits[tid][0];
        float val[TOPK]; int idx[TOPK];
        #pragma unroll
        for (int r = 0; r < TOPK; r++) { val[r] = -INFINITY; idx[r] = 0; }

        for (int e = 0; e < NEXP; e++) {
            float z = p[e] * SCALE_INV + __ldg(&bias[e]);
            float sc = 1.0f / (1.0f + __expf(-z));   // monotone: order preserved
            if (sc > val[TOPK - 1]) {                // strict >: first index wins ties
                int pos = TOPK - 1;
                while (pos > 0 && sc > val[pos - 1]) {
                    val[pos] = val[pos - 1]; idx[pos] = idx[pos - 1]; pos--;
                }
                val[pos] = sc; idx[pos] = e;
            }
        }

        int t = t0 + tid;
        #pragma unroll
        for (int r = 0; r < TOPK; r++) {
            out[(size_t)t * TOPK + r] = val[r];
            out[(size_t)N_TOK * TOPK + (size_t)t * TOPK + r] = (float)idx[r];
        }
    }
}

extern "C" void kernel_launch(void* const* d_in, const int* in_sizes, int n_in,
                              void* d_out, int out_size) {
    const float* x = (const float*)d_in[0];
    const float* W = (const float*)d_in[1];
    const float* b = (const float*)d_in[2];
    float* out = (float*)d_out;

    wprep_kernel<<<NKS * 256 / 256, 256>>>(W);
    router_kernel<<<N_TOK / TM, THREADS>>>(x, b, out);
}

// round 17
// speedup vs baseline: 2.0316x; 2.0316x over previous
#include <cuda_runtime.h>
#include <cuda_fp16.h>
#include <math.h>
#include <stdint.h>

#define N_TOK   16384
#define DDIM    2048
#define NEXP    64
#define TM      64
#define NKS     (DDIM / 16)     // 128 k-steps of 16
#define NCH     (DDIM / 64)     // 32 chunks of 64 k
#define TOPK    8
#define THREADS 256
#define LPAD    66

#define WSC       1024.0f           // 2^10 on W only
#define SCALE_INV 9.765625e-04f     // 2^-10

// B fragments (pi-permuted k), hi/lo interleaved: [ks][nb*32+lane]={hi0,hi1,lo0,lo1}
__device__ __align__(128) uint4 g_Bfrag[NKS * 256];

static __device__ __forceinline__ uint32_t h2u(__half2 h) {
    return reinterpret_cast<uint32_t&>(h);
}

static __device__ __forceinline__ void hmma(float* c, const uint32_t* a,
                                            uint32_t b0, uint32_t b1) {
    asm("mma.sync.aligned.m16n8k16.row.col.f32.f16.f16.f32 "
        "{%0,%1,%2,%3}, {%4,%5,%6,%7}, {%8,%9}, {%0,%1,%2,%3};"
        : "+f"(c[0]), "+f"(c[1]), "+f"(c[2]), "+f"(c[3])
        : "r"(a[0]), "r"(a[1]), "r"(a[2]), "r"(a[3]), "r"(b0), "r"(b1));
}

// split 2 floats -> hi half2 + lo residual half2
static __device__ __forceinline__ void split2(float v0, float v1,
                                              uint32_t& hi, uint32_t& lo) {
    __half2 h = __floats2half2_rn(v0, v1);
    float2 hf = __half22float2(h);
    __half2 r = __floats2half2_rn(v0 - hf.x, v1 - hf.y);
    hi = h2u(h); lo = h2u(r);
}

// r0 = row g float4, r1 = row g+8 float4 (one pi-permuted k-step)
static __device__ __forceinline__ void cvtf4(float4 r0, float4 r1,
                                             uint32_t* ahi, uint32_t* alo) {
    split2(r0.x, r0.y, ahi[0], alo[0]);
    split2(r1.x, r1.y, ahi[1], alo[1]);
    split2(r0.z, r0.w, ahi[2], alo[2]);
    split2(r1.z, r1.w, ahi[3], alo[3]);
}

// ---- prep: W -> pi-permuted fragments (lane t=l&3 slots hold cols 4t..4t+3) ----
__global__ void __launch_bounds__(256) wprep_kernel(const float* __restrict__ W) {
    int idx = blockIdx.x * 256 + threadIdx.x;        // 32768 = (ks, nb, lane)
    int l = idx & 31, nb = (idx >> 5) & 7, ks = idx >> 8;
    int n = nb * 8 + (l >> 2);
    int k = ks * 16 + (l & 3) * 4;
    float4 w = *(const float4*)(W + (size_t)n * DDIM + k);
    float a0 = w.x * WSC, a1 = w.y * WSC, a2 = w.z * WSC, a3 = w.w * WSC;
    uint32_t h0, l0, h1, l1;
    split2(a0, a1, h0, l0);
    split2(a2, a3, h1, l1);
    g_Bfrag[ks * 256 + nb * 32 + l] = make_uint4(h0, h1, l0, l1);
}

static __device__ __forceinline__ void ldB(uint4 b[8], const uint4* gb, int ks) {
    const uint4* p = gb + ks * 256;
    #pragma unroll
    for (int nb = 0; nb < 8; nb++) b[nb] = __ldg(p + nb * 32);
}

static __device__ __forceinline__ void mma_step(float acc[8][4],
                                                const uint32_t* ahi, const uint32_t* alo,
                                                const uint4 b[8]) {
    #pragma unroll
    for (int nb = 0; nb < 8; nb++) {
        hmma(acc[nb], ahi, b[nb].x, b[nb].y);
        hmma(acc[nb], ahi, b[nb].z, b[nb].w);
        hmma(acc[nb], alo, b[nb].x, b[nb].y);
    }
}

// ---- fused router: TM=64, 8 warps, kh-split pairs, zero mainloop sync ----
__global__ void __launch_bounds__(THREADS, 2)
router_kernel(const float* __restrict__ x, const float* __restrict__ bias,
              float* __restrict__ out) {
    __shared__ float logits[TM][LPAD];

    const int tid = threadIdx.x;
    const int wid = tid >> 5, l = tid & 31;
    const int rg  = wid & 3;           // row group: rows rg*16 .. rg*16+15
    const int kh  = wid >> 2;          // k half: ksteps 2kh, 2kh+1 of each chunk
    const int g = l >> 2, kq = (l & 3) * 4;
    const int t0 = blockIdx.x * TM;

    const float* xr0 = x + (size_t)(t0 + rg * 16 + g) * DDIM + kh * 32 + kq;
    const float* xr1 = xr0 + 8 * DDIM;
    const uint4* gb = g_Bfrag + l;

    float acc[8][4];
    #pragma unroll
    for (int nb = 0; nb < 8; nb++)
        #pragma unroll
        for (int c = 0; c < 4; c++) acc[nb][c] = 0.0f;

    // A raw for chunk 0: this warp's 2 k-steps (4 x LDG.128)
    float4 raw[4];
    #pragma unroll
    for (int s = 0; s < 2; s++) {
        raw[s * 2 + 0] = *(const float4*)(xr0 + s * 16);
        raw[s * 2 + 1] = *(const float4*)(xr1 + s * 16);
    }
    // prime L2 for chunk 1
    asm volatile("prefetch.global.L2 [%0];" :: "l"(xr0 + 64));
    asm volatile("prefetch.global.L2 [%0];" :: "l"(xr1 + 64));

    uint4 bc[8], bn[8];
    ldB(bc, gb, 2 * kh);                  // first k-step of chunk 0 for this warp

    for (int c = 0; c < NCH; c++) {
        const int ksA = c * 4 + 2 * kh;   // this warp's first kstep in chunk c
        const int kn = ((c + 1 < NCH) ? (c + 1) : c) * 64;

        // hoisted: give bn extra load-use distance over the cvt block
        ldB(bn, gb, ksA + 1);

        // register-free deep prefetch: chunk c+2 into L2
        if (c + 2 < NCH) {
            const int kn2 = (c + 2) * 64;
            asm volatile("prefetch.global.L2 [%0];" :: "l"(xr0 + kn2));
            asm volatile("prefetch.global.L2 [%0];" :: "l"(xr1 + kn2));
        }

        uint32_t ahi0[4], alo0[4], ahi1[4], alo1[4];
        cvtf4(raw[0], raw[1], ahi0, alo0);
        cvtf4(raw[2], raw[3], ahi1, alo1);

        // demand A for next chunk (should now hit L2)
        #pragma unroll
        for (int s = 0; s < 2; s++) {
            raw[s * 2 + 0] = *(const float4*)(xr0 + kn + s * 16);
            raw[s * 2 + 1] = *(const float4*)(xr1 + kn + s * 16);
        }

        mma_step(acc, ahi0, alo0, bc);
        ldB(bc, gb, (c + 1 < NCH) ? ksA + 4 : ksA + 1);   // next chunk's first
        mma_step(acc, ahi1, alo1, bn);
    }

    // ---- combine warp-pair partials in smem logits, then top-8 ----
    const int r0 = rg * 16 + g;
    const int kp = (l & 3) * 2;          // D-frag columns (unpermuted)
    if (kh == 0) {
        #pragma unroll
        for (int nb = 0; nb < 8; nb++) {
            int c0 = nb * 8 + kp;
            *(float2*)&logits[r0][c0]     = make_float2(acc[nb][0], acc[nb][1]);
            *(float2*)&logits[r0 + 8][c0] = make_float2(acc[nb][2], acc[nb][3]);
        }
    }
    __syncthreads();
    if (kh == 1) {
        #pragma unroll
        for (int nb = 0; nb < 8; nb++) {
            int c0 = nb * 8 + kp;
            float2 p0 = *(float2*)&logits[r0][c0];
            float2 p1 = *(float2*)&logits[r0 + 8][c0];
            *(float2*)&logits[r0][c0] =
                make_float2(p0.x + acc[nb][0], p0.y + acc[nb][1]);
            *(float2*)&logits[r0 + 8][c0] =
                make_float2(p1.x + acc[nb][2], p1.y + acc[nb][3]);
        }
    }
    __syncthreads();

    if (tid < TM) {
        const float* p = &logits[tid][0];
        float val[TOPK]; int idx[TOPK];
        #pragma unroll
        for (int r = 0; r < TOPK; r++) { val[r] = -INFINITY; idx[r] = 0; }

        for (int e = 0; e < NEXP; e++) {
            float z = p[e] * SCALE_INV + __ldg(&bias[e]);
            float sc = 1.0f / (1.0f + __expf(-z));   // monotone: order preserved
            if (sc > val[TOPK - 1]) {                // strict >: first index wins ties
                int pos = TOPK - 1;
                while (pos > 0 && sc > val[pos - 1]) {
                    val[pos] = val[pos - 1]; idx[pos] = idx[pos - 1]; pos--;
                }
                val[pos] = sc; idx[pos] = e;
            }
        }

        int t = t0 + tid;
        #pragma unroll
        for (int r = 0; r < TOPK; r++) {
            out[(size_t)t * TOPK + r] = val[r];
            out[(size_t)N_TOK * TOPK + (size_t)t * TOPK + r] = (float)idx[r];
        }
    }
}

extern "C" void kernel_launch(void* const* d_in, const int* in_sizes, int n_in,
                              void* d_out, int out_size) {
    const float* x = (const float*)d_in[0];
    const float* W = (const float*)d_in[1];
    const float* b = (const float*)d_in[2];
    float* out = (float*)d_out;

    wprep_kernel<<<NKS * 256 / 256, 256>>>(W);
    router_kernel<<<N_TOK / TM, THREADS>>>(x, b, out);
}